// round 16
// baseline (speedup 1.0000x reference)
#include <cuda_runtime.h>
#include <math_constants.h>

// ---------------------------------------------------------------------------
// AffineChamferLoss: exact NN via anisotropic 16^3 CSR grid.
// K1 (persistent, grid barriers): transform+moments -> grid geometry ->
//     count -> single-block-per-set scan -> scatter.
// K2: HALF-WARP-PER-QUERY exact NN (2 spatially-adjacent queries per warp,
//     16-lane sub-warps with per-sub masks):
//     home-cell scan + 16-pt sample upper bound; x-slab batches (ix=b) over
//     the exact interval [floor(rx-sqrt(best)/hx), floor(rx+sqrt(best)/hx)]
//     (clamped; boundary columns open-ended outward -> exact superset).
//     Surviving columns: per-lane exact dxy^2 prune + exact arithmetic
//     z-range (one contiguous CSR range), scanned sub-warp-strided
//     (coalesced) via ballot + shfl (ABSOLUTE lane index - R15 bugfix).
//     Exhaustive + exact prune => exact.
// ---------------------------------------------------------------------------

#define NMAX   16384
#define G      16
#define CELLS  (G * G * G)     // 4096
#define INFF   3.0e38f
#define NBLKMX 512
#define FULLM  0xffffffffu

__device__ float4   g_xbuf[NMAX];         // transformed moving pts (set 1)
__device__ float4   g_ybuf[NMAX];         // fixed pts              (set 0)
__device__ int      g_cellid[2][NMAX];
__device__ unsigned g_cnt[2][CELLS];
__device__ int      g_start[2][CELLS + 16];
__device__ unsigned g_cur[2][CELLS];
__device__ float4   g_sort[2][NMAX];
__device__ float    g_mpart[2][NBLKMX][6];

struct GridI {
    float mnx, mny, mnz;
    float hx, hy, hz;
    float ivx, ivy, ivz;
};
__device__ GridI g_grid[2];

// ---- software grid barrier -------------------------------------------------
__device__ unsigned           g_bar_count = 0;
__device__ volatile unsigned  g_bar_gen   = 0;

__device__ __forceinline__ void grid_barrier() {
    __syncthreads();
    if (threadIdx.x == 0) {
        unsigned gen = g_bar_gen;
        __threadfence();
        unsigned prev = atomicAdd(&g_bar_count, 1u);
        if (prev == gridDim.x - 1) {
            g_bar_count = 0;
            __threadfence();
            g_bar_gen = gen + 1;
        } else {
            while (g_bar_gen == gen) __nanosleep(32);
            __threadfence();
        }
    }
    __syncthreads();
}

// ---- helpers ---------------------------------------------------------------
__device__ __forceinline__ float axdist(float q, float mn, float h, int i) {
    float lo = fmaf((float)i, h, mn);
    float dl = (i > 0)     ? (lo - q)       : -INFF;
    float dr = (i < G - 1) ? (q - (lo + h)) : -INFF;
    return fmaxf(0.0f, fmaxf(dl, dr));
}

// min over a 16-lane sub-warp (mask = the sub's 16 lanes; xor stays in-sub)
__device__ __forceinline__ float sub_min(unsigned m, float v) {
#pragma unroll
    for (int o = 8; o; o >>= 1)
        v = fminf(v, __shfl_xor_sync(m, v, o));
    return v;
}

__device__ __forceinline__ unsigned excl_scan_256(unsigned v, unsigned* wsm) {
    int lane = threadIdx.x & 31, wp = threadIdx.x >> 5;
    unsigned inc = v;
#pragma unroll
    for (int o = 1; o < 32; o <<= 1) {
        unsigned n = __shfl_up_sync(FULLM, inc, o);
        if (lane >= o) inc += n;
    }
    if (lane == 31) wsm[wp] = inc;
    __syncthreads();
    if (wp == 0) {
        unsigned ws = (lane < 8) ? wsm[lane] : 0u;
#pragma unroll
        for (int o = 1; o < 8; o <<= 1) {
            unsigned n = __shfl_up_sync(FULLM, ws, o);
            if (lane >= o) ws += n;
        }
        if (lane < 8) wsm[lane] = ws;
    }
    __syncthreads();
    unsigned off = wp ? wsm[wp - 1] : 0u;
    return off + inc - v;
}

// ---------------------------------------------------------------------------
// K1: fused setup (phases A-E) with grid barriers
__global__ void __launch_bounds__(256, 2)
setup_kernel(const float* __restrict__ fx,
             const float* __restrict__ mv,
             const float* __restrict__ mat,
             const float* __restrict__ tr,
             int nf, int nm, float* out) {
    __shared__ float    smom[12];
    __shared__ float    bb[12];
    __shared__ unsigned swsm[8];

    const int nblk = gridDim.x;
    const int bid  = blockIdx.x;
    const int t    = threadIdx.x;
    const int tid  = bid * 256 + t;
    const int nthr = nblk * 256;
    const int lane = t & 31, wid = t >> 5;
    const int nmax = nf > nm ? nf : nm;

    // ---- Phase A: transform + moments + zero counts/out ----
    if (t < 12) smom[t] = 0.0f;
    __syncthreads();

    float mom[12];
#pragma unroll
    for (int a = 0; a < 12; a++) mom[a] = 0.0f;

    for (int i = tid; i < nmax; i += nthr) {
        if (i < nm) {
            float p0 = mv[3*i+0], p1 = mv[3*i+1], p2 = mv[3*i+2];
            float x0 = fmaf(p2, mat[6], fmaf(p1, mat[3], fmaf(p0, mat[0], tr[0])));
            float x1 = fmaf(p2, mat[7], fmaf(p1, mat[4], fmaf(p0, mat[1], tr[1])));
            float x2 = fmaf(p2, mat[8], fmaf(p1, mat[5], fmaf(p0, mat[2], tr[2])));
            g_xbuf[i] = make_float4(x0, x1, x2, 0.0f);
            mom[6] += x0; mom[7]  += x1;      mom[8]  += x2;
            mom[9] += x0 * x0; mom[10] += x1 * x1; mom[11] += x2 * x2;
        }
        if (i < nf) {
            float y0 = fx[3*i+0], y1 = fx[3*i+1], y2 = fx[3*i+2];
            g_ybuf[i] = make_float4(y0, y1, y2, 0.0f);
            mom[0] += y0; mom[1] += y1; mom[2] += y2;
            mom[3] += y0 * y0; mom[4] += y1 * y1; mom[5] += y2 * y2;
        }
    }
#pragma unroll
    for (int a = 0; a < 12; a++) {
        float v = mom[a];
#pragma unroll
        for (int o = 16; o; o >>= 1) v += __shfl_down_sync(FULLM, v, o);
        if (lane == 0) atomicAdd(&smom[a], v);
    }
    __syncthreads();
    if (t < 12) g_mpart[t / 6][bid][t % 6] = smom[t];

    {
        unsigned* cn = &g_cnt[0][0];
        for (int k = tid; k < 2 * CELLS; k += nthr) cn[k] = 0u;
    }
    if (tid == 0) out[0] = 0.0f;
    grid_barrier();

    // ---- Phase B: grid geometry (block 0) ----
    if (bid == 0) {
        for (int slot = wid; slot < 12; slot += 8) {
            int s = slot / 6, k = slot % 6;
            float v = 0.0f;
            for (int j = lane; j < nblk; j += 32) v += g_mpart[s][j][k];
#pragma unroll
            for (int o = 16; o; o >>= 1) v += __shfl_down_sync(FULLM, v, o);
            if (lane == 0) bb[slot] = v;
        }
        __syncthreads();
        if (t < 2) {
            int s = t;
            float n = (float)(s ? nm : nf);
            float inv = 1.0f / n;
            float mean[3], sig[3];
#pragma unroll
            for (int a = 0; a < 3; a++) {
                mean[a] = bb[s*6+a] * inv;
                float var = bb[s*6+3+a] * inv - mean[a] * mean[a];
                sig[a] = sqrtf(fmaxf(var, 1e-8f));
            }
            GridI gi;
            gi.mnx = mean[0] - 3.0f * sig[0];
            gi.mny = mean[1] - 3.0f * sig[1];
            gi.mnz = mean[2] - 3.0f * sig[2];
            gi.hx = 6.0f * sig[0] / (float)G;
            gi.hy = 6.0f * sig[1] / (float)G;
            gi.hz = 6.0f * sig[2] / (float)G;
            gi.ivx = 1.0f / gi.hx; gi.ivy = 1.0f / gi.hy; gi.ivz = 1.0f / gi.hz;
            g_grid[s] = gi;
        }
    }
    grid_barrier();

    // ---- Phase C: cell ids + counts ----
    {
        GridI ga = g_grid[0], gb = g_grid[1];
        for (int i = tid; i < nmax; i += nthr) {
            if (i < nf) {
                float4 p = g_ybuf[i];
                int ix = min(G - 1, max(0, (int)floorf((p.x - ga.mnx) * ga.ivx)));
                int iy = min(G - 1, max(0, (int)floorf((p.y - ga.mny) * ga.ivy)));
                int iz = min(G - 1, max(0, (int)floorf((p.z - ga.mnz) * ga.ivz)));
                int c = (ix << 8) | (iy << 4) | iz;
                g_cellid[0][i] = c;
                atomicAdd(&g_cnt[0][c], 1u);
            }
            if (i < nm) {
                float4 p = g_xbuf[i];
                int ix = min(G - 1, max(0, (int)floorf((p.x - gb.mnx) * gb.ivx)));
                int iy = min(G - 1, max(0, (int)floorf((p.y - gb.mny) * gb.ivy)));
                int iz = min(G - 1, max(0, (int)floorf((p.z - gb.mnz) * gb.ivz)));
                int c = (ix << 8) | (iy << 4) | iz;
                g_cellid[1][i] = c;
                atomicAdd(&g_cnt[1][c], 1u);
            }
        }
    }
    grid_barrier();

    // ---- Phase D: CSR scan, one block per set (4096 = 256 x 16) ----
    if (bid < 2) {
        int s = bid;
        const uint4* c4 = reinterpret_cast<const uint4*>(&g_cnt[s][0]);
        unsigned cnts[16];
#pragma unroll
        for (int j = 0; j < 4; j++) {
            uint4 v = c4[t * 4 + j];
            cnts[j*4+0] = v.x; cnts[j*4+1] = v.y;
            cnts[j*4+2] = v.z; cnts[j*4+3] = v.w;
        }
        unsigned tot = 0;
#pragma unroll
        for (int j = 0; j < 16; j++) tot += cnts[j];

        unsigned e = excl_scan_256(tot, swsm);

        unsigned run = e;
        int st[16];
#pragma unroll
        for (int j = 0; j < 16; j++) { st[j] = (int)run; run += cnts[j]; }

        int4* st4 = reinterpret_cast<int4*>(&g_start[s][0]);
        int4* cu4 = reinterpret_cast<int4*>(&g_cur[s][0]);
#pragma unroll
        for (int j = 0; j < 4; j++) {
            int4 v = make_int4(st[j*4+0], st[j*4+1], st[j*4+2], st[j*4+3]);
            st4[t * 4 + j] = v;
            cu4[t * 4 + j] = v;
        }
        if (t == 255) g_start[s][CELLS] = (int)run;
    }
    grid_barrier();

    // ---- Phase E: scatter into CSR order ----
    for (int i = tid; i < nmax; i += nthr) {
        if (i < nf) {
            int c = g_cellid[0][i];
            unsigned p = atomicAdd(&g_cur[0][c], 1u);
            g_sort[0][p] = g_ybuf[i];
        }
        if (i < nm) {
            int c = g_cellid[1][i];
            unsigned p = atomicAdd(&g_cur[1][c], 1u);
            g_sort[1][p] = g_xbuf[i];
        }
    }
}

// ---------------------------------------------------------------------------
// K2: HALF-WARP-PER-QUERY exact NN (2 queries/warp, 16-lane sub-warps)
__global__ void __launch_bounds__(256)
query_kernel(float* out, int nm, int nf) {
    const int lane = threadIdx.x & 31, wid = threadIdx.x >> 5;
    const int sub = lane >> 4, sl = lane & 15;
    const unsigned smask = 0xFFFFu << (sub << 4);
    const int task = (blockIdx.x * 8 + wid) * 2 + sub;
    const int ntask = nm + nf;

    float res = 0.0f;
    if (task < ntask) {
        int dir = (task < nm) ? 0 : 1;
        int qi  = dir ? (task - nm) : task;
        const int nq = dir ? nf : nm;
        const int nt = dir ? nm : nf;
        const float4* __restrict__ qb = g_sort[1 - dir];
        const float4* __restrict__ tb = g_sort[dir];
        const int*    __restrict__ cs = &g_start[dir][0];
        GridI gi = g_grid[dir];

        float4 q = qb[qi];
        float rx = (q.x - gi.mnx) * gi.ivx;
        float ry = (q.y - gi.mny) * gi.ivy;
        float rz = (q.z - gi.mnz) * gi.ivz;
        int cx = min(G - 1, max(0, (int)floorf(rx)));
        int cy = min(G - 1, max(0, (int)floorf(ry)));
        int cz = min(G - 1, max(0, (int)floorf(rz)));

        // ---- upper bound: home cell (sub-strided) + 16-pt strided sample
        float lb = INFF;
        {
            int home = (cx << 8) | (cy << 4) | cz;
            int s0 = cs[home], e0 = cs[home + 1];
            for (int p = s0 + sl; p < e0; p += 16) {
                float4 tp = tb[p];
                float ax = tp.x - q.x, ay = tp.y - q.y, az = tp.z - q.z;
                lb = fminf(lb, fmaf(ax, ax, fmaf(ay, ay, az * az)));
            }
            int p = sl * (nt >> 4);
            if (p < nt) {
                float4 tp = tb[p];
                float ax = tp.x - q.x, ay = tp.y - q.y, az = tp.z - q.z;
                lb = fminf(lb, fmaf(ax, ax, fmaf(ay, ay, az * az)));
            }
        }
        float best = sub_min(smask, lb);
        lb = best;

        // exact x-interval of candidate x-slabs (clamped; boundary columns
        // open-ended outward so the clamp preserves the superset)
        float sb = sqrtf(best) * gi.ivx;
        int xlo = min(G - 1, max(0, (int)floorf(rx - sb)));
        int xhi = min(G - 1, max(0, (int)floorf(rx + sb)));

        // ---- sweep: x-slab batches, batch b = ix=b, lanes cover 16 iy ----
        for (int b = xlo; b <= xhi; ++b) {
            int ix = b, iy = sl;
            float ddx = axdist(q.x, gi.mnx, gi.hx, ix);
            float ddy = axdist(q.y, gi.mny, gi.hy, iy);
            float dxy2 = fmaf(ddx, ddx, ddy * ddy);
            int s0 = 0, e0 = 0;
            float rem = best - dxy2;
            if (rem > 0.0f) {
                float sv = sqrtf(rem) * gi.ivz;
                int zlo = min(G - 1, max(0, (int)floorf(rz - sv)));
                int zhi = min(G - 1, max(0, (int)floorf(rz + sv)));
                int cbase = (ix << 8) | (iy << 4);
                s0 = cs[cbase + zlo];
                e0 = cs[cbase + zhi + 1];
            }
            unsigned mask = __ballot_sync(smask, e0 > s0) & smask;
            if (mask) {
                while (mask) {
                    int src = __ffs(mask) - 1;     // ABSOLUTE lane index
                    mask &= mask - 1;
                    int ss = __shfl_sync(smask, s0, src);
                    int ee = __shfl_sync(smask, e0, src);
                    for (int p = ss + sl; p < ee; p += 16) {
                        float4 tp = tb[p];
                        float ax = tp.x - q.x, ay = tp.y - q.y, az = tp.z - q.z;
                        lb = fminf(lb, fmaf(ax, ax, fmaf(ay, ay, az * az)));
                    }
                }
                best = sub_min(smask, lb);
                lb = best;
            }
        }
        res = (sl == 0) ? best / (float)nq : 0.0f;
    }

    // block reduce + atomicAdd
    float acc = res;
#pragma unroll
    for (int o = 16; o; o >>= 1) acc += __shfl_down_sync(FULLM, acc, o);
    __shared__ float ws[8];
    if (lane == 0) ws[wid] = acc;
    __syncthreads();
    if (wid == 0) {
        float v = (lane < 8) ? ws[lane] : 0.0f;
#pragma unroll
        for (int o = 4; o; o >>= 1) v += __shfl_down_sync(FULLM, v, o);
        if (lane == 0) atomicAdd(out, v);
    }
}

// ---------------------------------------------------------------------------
extern "C" void kernel_launch(void* const* d_in, const int* in_sizes, int n_in,
                              void* d_out, int out_size) {
    const float* fx  = (const float*)d_in[0];
    const float* mv  = (const float*)d_in[1];
    const float* mat = (const float*)d_in[2];
    const float* tr  = (const float*)d_in[3];
    float* out = (float*)d_out;

    int nf = in_sizes[0] / 3;
    int nm = in_sizes[1] / 3;

    int nblk = 128;                     // setup: cheap barriers, 1 item/thread

    setup_kernel<<<nblk, 256>>>(fx, mv, mat, tr, nf, nm, out);

    int ntask = nm + nf;
    int qblocks = (ntask + 15) / 16;    // 2 tasks per warp, 8 warps per block
    query_kernel<<<qblocks, 256>>>(out, nm, nf);
}

// round 17
// speedup vs baseline: 1.0560x; 1.0560x over previous
#include <cuda_runtime.h>
#include <math_constants.h>

// ---------------------------------------------------------------------------
// AffineChamferLoss: exact NN via anisotropic 16^3 CSR grid.
// K1 (persistent, 128 blocks, grid barriers): transform+moments -> grid
//     geometry -> count -> single-block-per-set scan -> scatter.
// K2: WARP-PER-QUERY exact NN (R14 structure, verified 55us):
//     home-cell scan + 32-pt sample upper bound, then 8 batches of 32
//     z-columns (batch b covers ix in {2b,2b+1}); batches outside the exact
//     x-interval [floor(rx-sqrt(best)/hx), floor(rx+sqrt(best)/hx)] (clamped,
//     boundary columns open-ended outward) are skipped warp-uniformly.
//     Surviving columns: per-lane exact dxy^2 prune + exact arithmetic
//     z-range (one contiguous CSR range), scanned lane-strided (coalesced)
//     via ballot + shfl broadcast. Exhaustive + exact prune => exact.
// ---------------------------------------------------------------------------

#define NMAX   16384
#define G      16
#define CELLS  (G * G * G)     // 4096
#define INFF   3.0e38f
#define NBLKMX 512
#define FULLM  0xffffffffu

__device__ float4   g_xbuf[NMAX];         // transformed moving pts (set 1)
__device__ float4   g_ybuf[NMAX];         // fixed pts              (set 0)
__device__ int      g_cellid[2][NMAX];
__device__ unsigned g_cnt[2][CELLS];
__device__ int      g_start[2][CELLS + 16];
__device__ unsigned g_cur[2][CELLS];
__device__ float4   g_sort[2][NMAX];
__device__ float    g_mpart[2][NBLKMX][6];

struct GridI {
    float mnx, mny, mnz;
    float hx, hy, hz;
    float ivx, ivy, ivz;
};
__device__ GridI g_grid[2];

// ---- software grid barrier -------------------------------------------------
__device__ unsigned           g_bar_count = 0;
__device__ volatile unsigned  g_bar_gen   = 0;

__device__ __forceinline__ void grid_barrier() {
    __syncthreads();
    if (threadIdx.x == 0) {
        unsigned gen = g_bar_gen;
        __threadfence();
        unsigned prev = atomicAdd(&g_bar_count, 1u);
        if (prev == gridDim.x - 1) {
            g_bar_count = 0;
            __threadfence();
            g_bar_gen = gen + 1;
        } else {
            while (g_bar_gen == gen) __nanosleep(32);
            __threadfence();
        }
    }
    __syncthreads();
}

// ---- helpers ---------------------------------------------------------------
__device__ __forceinline__ float axdist(float q, float mn, float h, int i) {
    float lo = fmaf((float)i, h, mn);
    float dl = (i > 0)     ? (lo - q)       : -INFF;
    float dr = (i < G - 1) ? (q - (lo + h)) : -INFF;
    return fmaxf(0.0f, fmaxf(dl, dr));
}

__device__ __forceinline__ float warp_min(float v) {
#pragma unroll
    for (int o = 16; o; o >>= 1)
        v = fminf(v, __shfl_xor_sync(FULLM, v, o));
    return v;
}

__device__ __forceinline__ unsigned excl_scan_256(unsigned v, unsigned* wsm) {
    int lane = threadIdx.x & 31, wp = threadIdx.x >> 5;
    unsigned inc = v;
#pragma unroll
    for (int o = 1; o < 32; o <<= 1) {
        unsigned n = __shfl_up_sync(FULLM, inc, o);
        if (lane >= o) inc += n;
    }
    if (lane == 31) wsm[wp] = inc;
    __syncthreads();
    if (wp == 0) {
        unsigned ws = (lane < 8) ? wsm[lane] : 0u;
#pragma unroll
        for (int o = 1; o < 8; o <<= 1) {
            unsigned n = __shfl_up_sync(FULLM, ws, o);
            if (lane >= o) ws += n;
        }
        if (lane < 8) wsm[lane] = ws;
    }
    __syncthreads();
    unsigned off = wp ? wsm[wp - 1] : 0u;
    return off + inc - v;
}

// ---------------------------------------------------------------------------
// K1: fused setup (phases A-E) with grid barriers
__global__ void __launch_bounds__(256, 2)
setup_kernel(const float* __restrict__ fx,
             const float* __restrict__ mv,
             const float* __restrict__ mat,
             const float* __restrict__ tr,
             int nf, int nm, float* out) {
    __shared__ float    smom[12];
    __shared__ float    bb[12];
    __shared__ unsigned swsm[8];

    const int nblk = gridDim.x;
    const int bid  = blockIdx.x;
    const int t    = threadIdx.x;
    const int tid  = bid * 256 + t;
    const int nthr = nblk * 256;
    const int lane = t & 31, wid = t >> 5;
    const int nmax = nf > nm ? nf : nm;

    // ---- Phase A: transform + moments + zero counts/out ----
    if (t < 12) smom[t] = 0.0f;
    __syncthreads();

    float mom[12];
#pragma unroll
    for (int a = 0; a < 12; a++) mom[a] = 0.0f;

    for (int i = tid; i < nmax; i += nthr) {
        if (i < nm) {
            float p0 = mv[3*i+0], p1 = mv[3*i+1], p2 = mv[3*i+2];
            float x0 = fmaf(p2, mat[6], fmaf(p1, mat[3], fmaf(p0, mat[0], tr[0])));
            float x1 = fmaf(p2, mat[7], fmaf(p1, mat[4], fmaf(p0, mat[1], tr[1])));
            float x2 = fmaf(p2, mat[8], fmaf(p1, mat[5], fmaf(p0, mat[2], tr[2])));
            g_xbuf[i] = make_float4(x0, x1, x2, 0.0f);
            mom[6] += x0; mom[7]  += x1;      mom[8]  += x2;
            mom[9] += x0 * x0; mom[10] += x1 * x1; mom[11] += x2 * x2;
        }
        if (i < nf) {
            float y0 = fx[3*i+0], y1 = fx[3*i+1], y2 = fx[3*i+2];
            g_ybuf[i] = make_float4(y0, y1, y2, 0.0f);
            mom[0] += y0; mom[1] += y1; mom[2] += y2;
            mom[3] += y0 * y0; mom[4] += y1 * y1; mom[5] += y2 * y2;
        }
    }
#pragma unroll
    for (int a = 0; a < 12; a++) {
        float v = mom[a];
#pragma unroll
        for (int o = 16; o; o >>= 1) v += __shfl_down_sync(FULLM, v, o);
        if (lane == 0) atomicAdd(&smom[a], v);
    }
    __syncthreads();
    if (t < 12) g_mpart[t / 6][bid][t % 6] = smom[t];

    {
        unsigned* cn = &g_cnt[0][0];
        for (int k = tid; k < 2 * CELLS; k += nthr) cn[k] = 0u;
    }
    if (tid == 0) out[0] = 0.0f;
    grid_barrier();

    // ---- Phase B: grid geometry (block 0) ----
    if (bid == 0) {
        for (int slot = wid; slot < 12; slot += 8) {
            int s = slot / 6, k = slot % 6;
            float v = 0.0f;
            for (int j = lane; j < nblk; j += 32) v += g_mpart[s][j][k];
#pragma unroll
            for (int o = 16; o; o >>= 1) v += __shfl_down_sync(FULLM, v, o);
            if (lane == 0) bb[slot] = v;
        }
        __syncthreads();
        if (t < 2) {
            int s = t;
            float n = (float)(s ? nm : nf);
            float inv = 1.0f / n;
            float mean[3], sig[3];
#pragma unroll
            for (int a = 0; a < 3; a++) {
                mean[a] = bb[s*6+a] * inv;
                float var = bb[s*6+3+a] * inv - mean[a] * mean[a];
                sig[a] = sqrtf(fmaxf(var, 1e-8f));
            }
            GridI gi;
            gi.mnx = mean[0] - 3.0f * sig[0];
            gi.mny = mean[1] - 3.0f * sig[1];
            gi.mnz = mean[2] - 3.0f * sig[2];
            gi.hx = 6.0f * sig[0] / (float)G;
            gi.hy = 6.0f * sig[1] / (float)G;
            gi.hz = 6.0f * sig[2] / (float)G;
            gi.ivx = 1.0f / gi.hx; gi.ivy = 1.0f / gi.hy; gi.ivz = 1.0f / gi.hz;
            g_grid[s] = gi;
        }
    }
    grid_barrier();

    // ---- Phase C: cell ids + counts ----
    {
        GridI ga = g_grid[0], gb = g_grid[1];
        for (int i = tid; i < nmax; i += nthr) {
            if (i < nf) {
                float4 p = g_ybuf[i];
                int ix = min(G - 1, max(0, (int)floorf((p.x - ga.mnx) * ga.ivx)));
                int iy = min(G - 1, max(0, (int)floorf((p.y - ga.mny) * ga.ivy)));
                int iz = min(G - 1, max(0, (int)floorf((p.z - ga.mnz) * ga.ivz)));
                int c = (ix << 8) | (iy << 4) | iz;
                g_cellid[0][i] = c;
                atomicAdd(&g_cnt[0][c], 1u);
            }
            if (i < nm) {
                float4 p = g_xbuf[i];
                int ix = min(G - 1, max(0, (int)floorf((p.x - gb.mnx) * gb.ivx)));
                int iy = min(G - 1, max(0, (int)floorf((p.y - gb.mny) * gb.ivy)));
                int iz = min(G - 1, max(0, (int)floorf((p.z - gb.mnz) * gb.ivz)));
                int c = (ix << 8) | (iy << 4) | iz;
                g_cellid[1][i] = c;
                atomicAdd(&g_cnt[1][c], 1u);
            }
        }
    }
    grid_barrier();

    // ---- Phase D: CSR scan, one block per set (4096 = 256 x 16) ----
    if (bid < 2) {
        int s = bid;
        const uint4* c4 = reinterpret_cast<const uint4*>(&g_cnt[s][0]);
        unsigned cnts[16];
#pragma unroll
        for (int j = 0; j < 4; j++) {
            uint4 v = c4[t * 4 + j];
            cnts[j*4+0] = v.x; cnts[j*4+1] = v.y;
            cnts[j*4+2] = v.z; cnts[j*4+3] = v.w;
        }
        unsigned tot = 0;
#pragma unroll
        for (int j = 0; j < 16; j++) tot += cnts[j];

        unsigned e = excl_scan_256(tot, swsm);

        unsigned run = e;
        int st[16];
#pragma unroll
        for (int j = 0; j < 16; j++) { st[j] = (int)run; run += cnts[j]; }

        int4* st4 = reinterpret_cast<int4*>(&g_start[s][0]);
        int4* cu4 = reinterpret_cast<int4*>(&g_cur[s][0]);
#pragma unroll
        for (int j = 0; j < 4; j++) {
            int4 v = make_int4(st[j*4+0], st[j*4+1], st[j*4+2], st[j*4+3]);
            st4[t * 4 + j] = v;
            cu4[t * 4 + j] = v;
        }
        if (t == 255) g_start[s][CELLS] = (int)run;
    }
    grid_barrier();

    // ---- Phase E: scatter into CSR order ----
    for (int i = tid; i < nmax; i += nthr) {
        if (i < nf) {
            int c = g_cellid[0][i];
            unsigned p = atomicAdd(&g_cur[0][c], 1u);
            g_sort[0][p] = g_ybuf[i];
        }
        if (i < nm) {
            int c = g_cellid[1][i];
            unsigned p = atomicAdd(&g_cur[1][c], 1u);
            g_sort[1][p] = g_xbuf[i];
        }
    }
}

// ---------------------------------------------------------------------------
// K2: WARP-PER-QUERY exact NN, batched column sweep with x-interval batch skip
__global__ void __launch_bounds__(256)
query_kernel(float* out, int nm, int nf) {
    const int lane = threadIdx.x & 31, wid = threadIdx.x >> 5;
    const int task = blockIdx.x * 8 + wid;
    const int ntask = nm + nf;

    float res = 0.0f;
    if (task < ntask) {
        int dir = (task < nm) ? 0 : 1;
        int qi  = dir ? (task - nm) : task;
        const int nq = dir ? nf : nm;
        const int nt = dir ? nm : nf;
        const float4* __restrict__ qb = g_sort[1 - dir];
        const float4* __restrict__ tb = g_sort[dir];
        const int*    __restrict__ cs = &g_start[dir][0];
        GridI gi = g_grid[dir];

        float4 q = qb[qi];
        float rx = (q.x - gi.mnx) * gi.ivx;
        float ry = (q.y - gi.mny) * gi.ivy;
        float rz = (q.z - gi.mnz) * gi.ivz;
        int cx = min(G - 1, max(0, (int)floorf(rx)));
        int cy = min(G - 1, max(0, (int)floorf(ry)));
        int cz = min(G - 1, max(0, (int)floorf(rz)));

        // ---- upper bound: home cell (lane-strided) + 32-pt strided sample
        float lb = INFF;
        {
            int home = (cx << 8) | (cy << 4) | cz;
            int s0 = cs[home], e0 = cs[home + 1];
            for (int p = s0 + lane; p < e0; p += 32) {
                float4 tp = tb[p];
                float ax = tp.x - q.x, ay = tp.y - q.y, az = tp.z - q.z;
                lb = fminf(lb, fmaf(ax, ax, fmaf(ay, ay, az * az)));
            }
            int p = lane * (nt >> 5);
            if (p < nt) {
                float4 tp = tb[p];
                float ax = tp.x - q.x, ay = tp.y - q.y, az = tp.z - q.z;
                lb = fminf(lb, fmaf(ax, ax, fmaf(ay, ay, az * az)));
            }
        }
        float best = warp_min(lb);
        lb = best;

        // exact x-interval of candidate columns (clamped; boundary columns
        // are open-ended outward so the clamp preserves the superset)
        float sb = sqrtf(best) * gi.ivx;
        int xlo = min(G - 1, max(0, (int)floorf(rx - sb)));
        int xhi = min(G - 1, max(0, (int)floorf(rx + sb)));

        // ---- sweep of 256 z-columns, 8 batches of 32; batch b: ix in {2b,2b+1}
#pragma unroll
        for (int base = 0; base < G * G; base += 32) {
            int bx0 = base >> 4;                 // first ix of this batch
            if (bx0 + 1 < xlo || bx0 > xhi) continue;

            int col = base + lane;
            int ix = col >> 4, iy = col & 15;
            float ddx = axdist(q.x, gi.mnx, gi.hx, ix);
            float ddy = axdist(q.y, gi.mny, gi.hy, iy);
            float dxy2 = fmaf(ddx, ddx, ddy * ddy);
            int s0 = 0, e0 = 0;
            float rem = best - dxy2;
            if (rem > 0.0f) {
                float sv = sqrtf(rem) * gi.ivz;
                int zlo = min(G - 1, max(0, (int)floorf(rz - sv)));
                int zhi = min(G - 1, max(0, (int)floorf(rz + sv)));
                int cbase = (ix << 8) | (iy << 4);
                s0 = cs[cbase + zlo];
                e0 = cs[cbase + zhi + 1];
            }
            unsigned mask = __ballot_sync(FULLM, e0 > s0);
            if (mask) {
                while (mask) {
                    int src = __ffs(mask) - 1;
                    mask &= mask - 1;
                    int ss = __shfl_sync(FULLM, s0, src);
                    int ee = __shfl_sync(FULLM, e0, src);
                    for (int p = ss + lane; p < ee; p += 32) {
                        float4 tp = tb[p];
                        float ax = tp.x - q.x, ay = tp.y - q.y, az = tp.z - q.z;
                        lb = fminf(lb, fmaf(ax, ax, fmaf(ay, ay, az * az)));
                    }
                }
                best = warp_min(lb);
                lb = best;
            }
        }
        res = best / (float)nq;
    }

    // block reduce (one value per warp) + atomicAdd
    __shared__ float ws[8];
    if (lane == 0) ws[wid] = res;
    __syncthreads();
    if (wid == 0) {
        float acc = (lane < 8) ? ws[lane] : 0.0f;
#pragma unroll
        for (int o = 4; o; o >>= 1) acc += __shfl_down_sync(FULLM, acc, o);
        if (lane == 0) atomicAdd(out, acc);
    }
}

// ---------------------------------------------------------------------------
extern "C" void kernel_launch(void* const* d_in, const int* in_sizes, int n_in,
                              void* d_out, int out_size) {
    const float* fx  = (const float*)d_in[0];
    const float* mv  = (const float*)d_in[1];
    const float* mat = (const float*)d_in[2];
    const float* tr  = (const float*)d_in[3];
    float* out = (float*)d_out;

    int nf = in_sizes[0] / 3;
    int nm = in_sizes[1] / 3;

    int nblk = 128;                     // setup: cheap barriers, 1 item/thread

    setup_kernel<<<nblk, 256>>>(fx, mv, mat, tr, nf, nm, out);

    int ntask = nm + nf;
    query_kernel<<<(ntask + 7) / 8, 256>>>(out, nm, nf);
}